// round 1
// baseline (speedup 1.0000x reference)
#include <cuda_runtime.h>

#define TSTEPS 30
#define BLOCK  64
#define NBATCH 262144

constexpr int   WTOT   = 2432;                       // prepped weight floats in smem
constexpr float NLOG2E = -1.4426950408889634f;

typedef unsigned long long u64;

// ---------- packed fp32x2 helpers (sm_103a FFMA2 path) ----------
__device__ __forceinline__ u64 ffma2(u64 a, u64 b, u64 c) {
    u64 d; asm("fma.rn.f32x2 %0, %1, %2, %3;" : "=l"(d) : "l"(a), "l"(b), "l"(c)); return d;
}
__device__ __forceinline__ u64 splat2(float v) {
    u64 d; asm("mov.b64 %0, {%1, %1};" : "=l"(d) : "f"(v)); return d;
}
__device__ __forceinline__ u64 pack2(float x, float y) {
    u64 d; asm("mov.b64 %0, {%1, %2};" : "=l"(d) : "f"(x), "f"(y)); return d;
}
__device__ __forceinline__ float2 unpack2(u64 v) {
    float2 r; asm("mov.b64 {%0, %1}, %2;" : "=f"(r.x), "=f"(r.y) : "l"(v)); return r;
}
__device__ __forceinline__ float ex2f(float x){ float r; asm("ex2.approx.f32 %0, %1;" : "=f"(r) : "f"(x)); return r; }
__device__ __forceinline__ float rcpf(float x){ float r; asm("rcp.approx.f32 %0, %1;" : "=f"(r) : "f"(x)); return r; }

__device__ __forceinline__ int comboOff(int c){ return c < 2 ? c*128 : 256 + (c-2)*272; }

// ---------- per-direction constants: W_hh (5x16 pre-scaled) + biases in registers ----------
__device__ __forceinline__ void load_dir(const float* wbase, int D, u64* whhr, u64* bgi, u64* bgh)
{
    const float4* wh4 = (const float4*)(wbase + 16*D);
#pragma unroll
    for (int k = 0; k < 5; ++k)
#pragma unroll
        for (int qq = 0; qq < 4; ++qq) {
            float4 a = wh4[k*4+qq];
            whhr[k*8+qq*2+0] = pack2(a.x, a.y);
            whhr[k*8+qq*2+1] = pack2(a.z, a.w);
        }
    const float4* b4 = (const float4*)(wbase + 16*D + 80);
#pragma unroll
    for (int qq = 0; qq < 4; ++qq) { float4 a = b4[qq]; bgi[qq*2]=pack2(a.x,a.y); bgi[qq*2+1]=pack2(a.z,a.w); }
    const float4* b5 = (const float4*)(wbase + 16*D + 96);
#pragma unroll
    for (int qq = 0; qq < 4; ++qq) { float4 a = b5[qq]; bgh[qq*2]=pack2(a.x,a.y); bgh[qq*2+1]=pack2(a.z,a.w); }
}

// ---------- one GRU timestep; gates pre-scaled so sigmoid/tanh are ex2-based ----------
// slots: j=0..4 -> r gate, 5..9 -> z gate, 10..14 -> n gate, 15 pad
// r/z rows pre-scaled by -log2e: sig(s) = rcp(1 + 2^a), a = accumulated
// n rows pre-scaled by -2log2e: tanh(v) = 2*rcp(1 + 2^a) - 1
template<int D>
__device__ __forceinline__ void gru_step(const float4* __restrict__ wih4,
                                         const u64* whhr, const u64* bgi, const u64* bgh,
                                         const float* xin, float* h)
{
    u64 gi[8], gh[8];
#pragma unroll
    for (int p = 0; p < 8; ++p) { gi[p] = bgi[p]; gh[p] = bgh[p]; }
#pragma unroll
    for (int k = 0; k < D; ++k) {
        u64 xs = splat2(xin[k]);
        float4 w0 = wih4[k*4+0], w1 = wih4[k*4+1], w2 = wih4[k*4+2], w3 = wih4[k*4+3];
        gi[0] = ffma2(pack2(w0.x,w0.y), xs, gi[0]);
        gi[1] = ffma2(pack2(w0.z,w0.w), xs, gi[1]);
        gi[2] = ffma2(pack2(w1.x,w1.y), xs, gi[2]);
        gi[3] = ffma2(pack2(w1.z,w1.w), xs, gi[3]);
        gi[4] = ffma2(pack2(w2.x,w2.y), xs, gi[4]);
        gi[5] = ffma2(pack2(w2.z,w2.w), xs, gi[5]);
        gi[6] = ffma2(pack2(w3.x,w3.y), xs, gi[6]);
        gi[7] = ffma2(pack2(w3.z,w3.w), xs, gi[7]);
    }
#pragma unroll
    for (int k = 0; k < 5; ++k) {
        u64 hs = splat2(h[k]);
#pragma unroll
        for (int p = 0; p < 8; ++p) gh[p] = ffma2(whhr[k*8+p], hs, gh[p]);
    }
    float g[16], q[16];
#pragma unroll
    for (int p = 0; p < 8; ++p) {
        float2 a = unpack2(gi[p]); g[2*p] = a.x; g[2*p+1] = a.y;
        float2 c = unpack2(gh[p]); q[2*p] = c.x; q[2*p+1] = c.y;
    }
#pragma unroll
    for (int u = 0; u < 5; ++u) {
        float r  = rcpf(1.f + ex2f(g[u]   + q[u]));
        float z  = rcpf(1.f + ex2f(g[5+u] + q[5+u]));
        float a  = fmaf(r, q[10+u], g[10+u]);
        float nn = fmaf(2.f, rcpf(1.f + ex2f(a)), -1.f);
        h[u] = nn + z*(h[u] - nn);
    }
}

__device__ __forceinline__ void read_in(const float2* buf, int tid, int t, float* xin)
{
    float2 p0 = buf[(t*6+0)*BLOCK+tid];
    float2 p1 = buf[(t*6+1)*BLOCK+tid];
    float2 p2 = buf[(t*6+2)*BLOCK+tid];
    float2 p3 = buf[(t*6+3)*BLOCK+tid];
    float2 p4 = buf[(t*6+4)*BLOCK+tid];
    float2 p5 = buf[(t*6+5)*BLOCK+tid];
    xin[0]=p0.x; xin[1]=p0.y; xin[2]=p1.x; xin[3]=p1.y; xin[4]=p2.x;
    xin[5]=p3.x; xin[6]=p3.y; xin[7]=p4.x; xin[8]=p4.y; xin[9]=p5.x;
}

#define BUF(t,p) buf[((t)*6+(p))*BLOCK + tid]

__global__ void __launch_bounds__(BLOCK)
gru_kernel(const float* __restrict__ x,
           const float* __restrict__ wih0, const float* __restrict__ whh0,
           const float* __restrict__ bih0, const float* __restrict__ bhh0,
           const float* __restrict__ wihU, const float* __restrict__ whhU,
           const float* __restrict__ bihU, const float* __restrict__ bhhU,
           float* __restrict__ out)
{
    extern __shared__ float smem[];
    float*  sw  = smem;                    // [WTOT] prepped weights
    float2* buf = (float2*)(smem + WTOT);  // [T][6][BLOCK] activations
    const int tid = threadIdx.x;

    // ---- cooperative weight prep: transpose, pad 15->16, pre-scale, merge biases ----
    for (int c = 0; c < 10; ++c) {
        int l = c >> 1, d = c & 1;
        int D = l ? 10 : 1;
        float* w = sw + comboOff(c);
        for (int i = tid; i < 16*D; i += BLOCK) {           // wihT[k][slot]
            int k = i >> 4, s = i & 15;
            float v = 0.f;
            if (s < 15) {
                float sc = (s < 10) ? NLOG2E : 2.f*NLOG2E;
                v = sc * (l == 0 ? wih0[d*15 + s]
                                 : wihU[(((l-1)*2 + d)*15 + s)*10 + k]);
            }
            w[i] = v;
        }
        float* wh = w + 16*D;
        for (int i = tid; i < 80; i += BLOCK) {             // whhT[k][slot]
            int k = i >> 4, s = i & 15;
            float v = 0.f;
            if (s < 15) {
                float sc = (s < 10) ? NLOG2E : 2.f*NLOG2E;
                v = sc * (l == 0 ? whh0[(d*15 + s)*5 + k]
                                 : whhU[(((l-1)*2 + d)*15 + s)*5 + k]);
            }
            wh[i] = v;
        }
        float* bg = wh + 80;                                // bias_gi (b_ih + b_hh for r,z; b_ih for n)
        for (int s = tid; s < 16; s += BLOCK) {
            float v = 0.f;
            if (s < 15) {
                float sc = (s < 10) ? NLOG2E : 2.f*NLOG2E;
                float bi = l == 0 ? bih0[d*15 + s] : bihU[((l-1)*2 + d)*15 + s];
                float bh = l == 0 ? bhh0[d*15 + s] : bhhU[((l-1)*2 + d)*15 + s];
                v = sc * (s < 10 ? (bi + bh) : bi);
            }
            bg[s] = v;
        }
        float* bh2 = bg + 16;                               // bias_gh (b_hh for n only)
        for (int s = tid; s < 16; s += BLOCK) {
            float v = 0.f;
            if (s >= 10 && s < 15) {
                float bh = l == 0 ? bhh0[d*15 + s] : bhhU[((l-1)*2 + d)*15 + s];
                v = 2.f*NLOG2E * bh;
            }
            bh2[s] = v;
        }
    }
    __syncthreads();
    // buffer is thread-private from here on; no further syncs needed

    const int b = blockIdx.x * BLOCK + tid;
    const float* xrow = x + (size_t)b * TSTEPS;

    u64 whhr[40], bgi[8], bgh[8];
    float h[5];

    // ===== layer 0 (D=1, input from gmem, writes buffer directly) =====
    {
        const float* w = sw + comboOff(0);
        load_dir(w, 1, whhr, bgi, bgh);
        const float4* wih4 = (const float4*)w;
#pragma unroll
        for (int u = 0; u < 5; ++u) h[u] = 0.f;
#pragma unroll 1
        for (int t = 0; t < TSTEPS; ++t) {
            float xin[1] = { xrow[t] };
            gru_step<1>(wih4, whhr, bgi, bgh, xin, h);
            BUF(t,0) = make_float2(h[0], h[1]);
            BUF(t,1) = make_float2(h[2], h[3]);
            BUF(t,2) = make_float2(h[4], 0.f);
        }
    }
    {
        const float* w = sw + comboOff(1);
        load_dir(w, 1, whhr, bgi, bgh);
        const float4* wih4 = (const float4*)w;
#pragma unroll
        for (int u = 0; u < 5; ++u) h[u] = 0.f;
#pragma unroll 1
        for (int tt = 0; tt < TSTEPS; ++tt) {
            int t = TSTEPS-1-tt;
            float xin[1] = { xrow[t] };
            gru_step<1>(wih4, whhr, bgi, bgh, xin, h);
            BUF(t,3) = make_float2(h[0], h[1]);
            BUF(t,4) = make_float2(h[2], h[3]);
            BUF(t,5) = make_float2(h[4], 0.f);
        }
    }

    // ===== layers 1..3: fwd stages into local scratch, bwd overwrites in place =====
    float2 fscr[3*TSTEPS];   // local memory (L1/L2-backed), 720B/thread
#pragma unroll 1
    for (int l = 1; l < 4; ++l) {
        {   // fwd
            const float* w = sw + comboOff(2*l);
            load_dir(w, 10, whhr, bgi, bgh);
            const float4* wih4 = (const float4*)w;
#pragma unroll
            for (int u = 0; u < 5; ++u) h[u] = 0.f;
#pragma unroll 1
            for (int t = 0; t < TSTEPS; ++t) {
                float xin[10]; read_in(buf, tid, t, xin);
                gru_step<10>(wih4, whhr, bgi, bgh, xin, h);
                fscr[t*3+0] = make_float2(h[0], h[1]);
                fscr[t*3+1] = make_float2(h[2], h[3]);
                fscr[t*3+2] = make_float2(h[4], 0.f);
            }
        }
        {   // bwd; after reading prev[t], overwrite both halves of slot t
            const float* w = sw + comboOff(2*l+1);
            load_dir(w, 10, whhr, bgi, bgh);
            const float4* wih4 = (const float4*)w;
#pragma unroll
            for (int u = 0; u < 5; ++u) h[u] = 0.f;
#pragma unroll 1
            for (int tt = 0; tt < TSTEPS; ++tt) {
                int t = TSTEPS-1-tt;
                float xin[10]; read_in(buf, tid, t, xin);
                gru_step<10>(wih4, whhr, bgi, bgh, xin, h);
                BUF(t,3) = make_float2(h[0], h[1]);
                BUF(t,4) = make_float2(h[2], h[3]);
                BUF(t,5) = make_float2(h[4], 0.f);
                BUF(t,0) = fscr[t*3+0];
                BUF(t,1) = fscr[t*3+1];
                BUF(t,2) = fscr[t*3+2];
            }
        }
    }

    // ===== layer 4: fwd full (keep only final h); bwd needs just ONE step (t=T-1) =====
    float hf[5];
    {
        const float* w = sw + comboOff(8);
        load_dir(w, 10, whhr, bgi, bgh);
        const float4* wih4 = (const float4*)w;
#pragma unroll
        for (int u = 0; u < 5; ++u) h[u] = 0.f;
#pragma unroll 1
        for (int t = 0; t < TSTEPS; ++t) {
            float xin[10]; read_in(buf, tid, t, xin);
            gru_step<10>(wih4, whhr, bgi, bgh, xin, h);
        }
#pragma unroll
        for (int u = 0; u < 5; ++u) hf[u] = h[u];
    }
    {
        const float* w = sw + comboOff(9);
        load_dir(w, 10, whhr, bgi, bgh);
        const float4* wih4 = (const float4*)w;
#pragma unroll
        for (int u = 0; u < 5; ++u) h[u] = 0.f;
        float xin[10]; read_in(buf, tid, TSTEPS-1, xin);
        gru_step<10>(wih4, whhr, bgi, bgh, xin, h);
    }

    float2* o2 = (float2*)(out + (size_t)b*10);
    o2[0] = make_float2(hf[0], hf[1]);
    o2[1] = make_float2(hf[2], hf[3]);
    o2[2] = make_float2(hf[4], h[0]);
    o2[3] = make_float2(h[1],  h[2]);
    o2[4] = make_float2(h[3],  h[4]);
}

extern "C" void kernel_launch(void* const* d_in, const int* in_sizes, int n_in,
                              void* d_out, int out_size)
{
    (void)in_sizes; (void)n_in; (void)out_size;
    const size_t smem = (size_t)WTOT*4 + (size_t)BLOCK*TSTEPS*6*sizeof(float2); // 101,888 B
    cudaFuncSetAttribute(gru_kernel, cudaFuncAttributeMaxDynamicSharedMemorySize, (int)smem);
    gru_kernel<<<NBATCH/BLOCK, BLOCK, smem>>>(
        (const float*)d_in[0],
        (const float*)d_in[1], (const float*)d_in[2],
        (const float*)d_in[3], (const float*)d_in[4],
        (const float*)d_in[5], (const float*)d_in[6],
        (const float*)d_in[7], (const float*)d_in[8],
        (float*)d_out);
}